// round 4
// baseline (speedup 1.0000x reference)
#include <cuda_runtime.h>

// Problem constants
#define BB 128
#define SS 2048
#define DD 128
#define YY 26

// Scratch for emit = X @ W  (27.3 MB). Static __device__ array: no allocation.
__device__ float g_emit[BB * SS * YY];

// ---------------------------------------------------------------------------
// Kernel 1: emit[row,y] = sum_d X[row,d] * W[d,y], replicating a cuBLAS
// "sliced1x4"-style K decomposition:
//   slice z (z=0..3) accumulates k in chunks [32t+8z, 32t+8z+8), t=0..3,
//   serially ascending with FFMA; partials combined ((s0+s1)+s2)+s3.
// One row per thread; W transposed into smem as Wt[y][d] for float4 access.
// ---------------------------------------------------------------------------
__global__ void __launch_bounds__(256) emit_kernel(const float* __restrict__ X,
                                                   const float* __restrict__ W) {
    __shared__ float Wt[YY * DD];  // Wt[y*128 + d] = W[d*26 + y]  (13312 B)
    int tid = threadIdx.x;
    for (int i = tid; i < YY * DD; i += 256) {
        int y = i / DD, d = i % DD;
        Wt[i] = W[d * YY + y];
    }
    __syncthreads();

    int row = blockIdx.x * 256 + tid;
    const float4* xr = (const float4*)(X + (size_t)row * DD);  // 32 float4
    const float4* wt4 = (const float4*)Wt;                     // [y][32]
    float* er = g_emit + (size_t)row * YY;

#pragma unroll 1
    for (int p = 0; p < 13; p++) {
        int y0 = 2 * p, y1 = 2 * p + 1;
        float s0[4], s1[4];
#pragma unroll
        for (int z = 0; z < 4; z++) { s0[z] = 0.f; s1[z] = 0.f; }

#pragma unroll
        for (int z = 0; z < 4; z++) {
#pragma unroll
            for (int t = 0; t < 4; t++) {
                int c = 8 * t + 2 * z;  // float4 index: chunk k = 32t+8z
                float4 xa = xr[c];
                float4 xb = xr[c + 1];
                float4 wa0 = wt4[y0 * 32 + c];
                float4 wb0 = wt4[y0 * 32 + c + 1];
                float4 wa1 = wt4[y1 * 32 + c];
                float4 wb1 = wt4[y1 * 32 + c + 1];
                // ascending k within the chunk, FMA (cublas FFMA style)
                s0[z] = fmaf(xa.x, wa0.x, s0[z]);
                s0[z] = fmaf(xa.y, wa0.y, s0[z]);
                s0[z] = fmaf(xa.z, wa0.z, s0[z]);
                s0[z] = fmaf(xa.w, wa0.w, s0[z]);
                s0[z] = fmaf(xb.x, wb0.x, s0[z]);
                s0[z] = fmaf(xb.y, wb0.y, s0[z]);
                s0[z] = fmaf(xb.z, wb0.z, s0[z]);
                s0[z] = fmaf(xb.w, wb0.w, s0[z]);
                s1[z] = fmaf(xa.x, wa1.x, s1[z]);
                s1[z] = fmaf(xa.y, wa1.y, s1[z]);
                s1[z] = fmaf(xa.z, wa1.z, s1[z]);
                s1[z] = fmaf(xa.w, wa1.w, s1[z]);
                s1[z] = fmaf(xb.x, wb1.x, s1[z]);
                s1[z] = fmaf(xb.y, wb1.y, s1[z]);
                s1[z] = fmaf(xb.z, wb1.z, s1[z]);
                s1[z] = fmaf(xb.w, wb1.w, s1[z]);
            }
        }
        // serial combine of the 4 k-slice partials
        float r0 = __fadd_rn(__fadd_rn(__fadd_rn(s0[0], s0[1]), s0[2]), s0[3]);
        float r1 = __fadd_rn(__fadd_rn(__fadd_rn(s1[0], s1[1]), s1[2]), s1[3]);
        er[y0] = r0;
        er[y1] = r1;
    }
}

// ---------------------------------------------------------------------------
// argmax over 26 values with FIRST-INDEX tie-breaking (matches jnp.argmax).
// Tree of 25 combines; left operand always covers lower indices, and we keep
// the left value on va >= vb, so the first maximum wins exactly.
// ---------------------------------------------------------------------------
__device__ __forceinline__ void argmax26(const float* v, float& mv, int& mi) {
    float a[13]; int ia[13];
#pragma unroll
    for (int k = 0; k < 13; k++) {
        bool p = v[2 * k] >= v[2 * k + 1];
        a[k] = p ? v[2 * k] : v[2 * k + 1];
        ia[k] = p ? 2 * k : 2 * k + 1;
    }
    float b[7]; int ib[7];
#pragma unroll
    for (int k = 0; k < 6; k++) {
        bool p = a[2 * k] >= a[2 * k + 1];
        b[k] = p ? a[2 * k] : a[2 * k + 1];
        ib[k] = p ? ia[2 * k] : ia[2 * k + 1];
    }
    b[6] = a[12]; ib[6] = ia[12];
    float c[4]; int ic[4];
#pragma unroll
    for (int k = 0; k < 3; k++) {
        bool p = b[2 * k] >= b[2 * k + 1];
        c[k] = p ? b[2 * k] : b[2 * k + 1];
        ic[k] = p ? ib[2 * k] : ib[2 * k + 1];
    }
    c[3] = b[6]; ic[3] = ib[6];
    bool p0 = c[0] >= c[1];
    float d0 = p0 ? c[0] : c[1]; int j0 = p0 ? ic[0] : ic[1];
    bool p1 = c[2] >= c[3];
    float d1 = p1 ? c[2] : c[3]; int j1 = p1 ? ic[2] : ic[3];
    bool pf = d0 >= d1;
    mv = pf ? d0 : d1;
    mi = pf ? j0 : j1;
}

// ---------------------------------------------------------------------------
// Kernel 2: Viterbi forward + backtrace. One warp per batch element.
// Exact float semantics of the reference:
//   lookup[i][y1] = max_yp ((em[i-1][yp] + T[yp][y1]) + lookup[i-1][yp])
//   bp[i][y1]     = first argmax of the same expression
// ---------------------------------------------------------------------------
__global__ void __launch_bounds__(32) viterbi_kernel(const float* __restrict__ Tm,
                                                     float* __restrict__ out) {
    extern __shared__ unsigned char sm[];
    unsigned char* bp = sm;                    // SS*YY bytes of backpointers
    float* lbuf = (float*)(sm + SS * YY);      // [2][32] lookup double-buffer
    float* ebuf = lbuf + 64;                   // [2][32] emit-row double-buffer

    int b = blockIdx.x;
    int lane = threadIdx.x;
    int y1 = lane < YY ? lane : YY - 1;

    float Tc[YY];
#pragma unroll
    for (int yp = 0; yp < YY; yp++) Tc[yp] = Tm[yp * YY + y1];

    const float* eb = g_emit + (size_t)b * SS * YY;

    lbuf[lane] = 0.f;
    lbuf[32 + lane] = 0.f;
    ebuf[lane] = 0.f;
    ebuf[32 + lane] = 0.f;
    float ev_ready = 0.f, ev_fly = 0.f;
    if (lane < YY) {
        ebuf[lane] = eb[lane];           // em[0] -> parity 0
        ev_ready = eb[YY + lane];        // em[1]
        ev_fly = eb[2 * YY + lane];      // em[2]
    }
    __syncwarp();

#pragma unroll 2
    for (int i = 1; i < SS; i++) {
        int pp = (i - 1) & 1;
        int p = i & 1;

        float e[28], lv[28];
        const float4* e4 = (const float4*)(ebuf + pp * 32);
        const float4* l4 = (const float4*)(lbuf + pp * 32);
#pragma unroll
        for (int k = 0; k < 7; k++) {
            float4 te = e4[k];
            float4 tl = l4[k];
            e[4 * k + 0] = te.x; e[4 * k + 1] = te.y; e[4 * k + 2] = te.z; e[4 * k + 3] = te.w;
            lv[4 * k + 0] = tl.x; lv[4 * k + 1] = tl.y; lv[4 * k + 2] = tl.z; lv[4 * k + 3] = tl.w;
        }

        float v[YY];
#pragma unroll
        for (int yp = 0; yp < YY; yp++) v[yp] = __fadd_rn(__fadd_rn(e[yp], Tc[yp]), lv[yp]);

        float m; int idx;
        argmax26(v, m, idx);

        if (lane < YY) {
            bp[i * YY + lane] = (unsigned char)idx;
            lbuf[p * 32 + lane] = m;          // lookup[i]
            ebuf[p * 32 + lane] = ev_ready;   // em[i]
        }
        ev_ready = ev_fly;
        if (lane < YY && (i + 2) < SS) ev_fly = eb[(size_t)(i + 2) * YY + lane];
        __syncwarp();
    }

    // last = argmax(em[S-1] + lookup[S-1])
    int pl = (SS - 1) & 1;
    float vv[YY];
#pragma unroll
    for (int y = 0; y < YY; y++) vv[y] = __fadd_rn(ebuf[pl * 32 + y], lbuf[pl * 32 + y]);
    float mm; int last;
    argmax26(vv, mm, last);

    // Backtrace + one-hot output (covers every output element)
    float* ob = out + (size_t)b * SS * YY;
    int nxt = last;
    if (lane < YY) ob[(size_t)(SS - 1) * YY + lane] = (lane == nxt) ? 1.f : 0.f;
    for (int i = SS - 2; i >= 0; i--) {
        nxt = bp[(i + 1) * YY + nxt];
        if (lane < YY) ob[(size_t)i * YY + lane] = (lane == nxt) ? 1.f : 0.f;
    }
}

// ---------------------------------------------------------------------------
extern "C" void kernel_launch(void* const* d_in, const int* in_sizes, int n_in,
                              void* d_out, int out_size) {
    const float* X = (const float*)d_in[0];   // [B,S,D]
    const float* W = (const float*)d_in[1];   // [D,Y]
    const float* T = (const float*)d_in[2];   // [Y,Y]
    float* out = (float*)d_out;               // [B,S,Y] fp32

    emit_kernel<<<(BB * SS) / 256, 256>>>(X, W);

    int smem = SS * YY + 2 * 64 * (int)sizeof(float);  // 53248 + 512 = 53760
    cudaFuncSetAttribute(viterbi_kernel,
                         cudaFuncAttributeMaxDynamicSharedMemorySize, smem);
    viterbi_kernel<<<BB, 32, smem>>>(T, out);
}

// round 5
// speedup vs baseline: 1.1929x; 1.1929x over previous
#include <cuda_runtime.h>
#include <string.h>

// Problem constants
#define BB 128
#define SS 2048
#define DD 128
#define YY 26

// Scratch for emit = X @ W  (27.3 MB). Static __device__ array: no allocation.
__device__ float g_emit[BB * SS * YY];

// ---------------------------------------------------------------------------
// Packed f32x2 add (two independent fadd.rn — bit-exact vs scalar __fadd_rn).
// ---------------------------------------------------------------------------
__device__ __forceinline__ float2 addx2(float2 a, float2 b) {
    unsigned long long ua, ub, ur;
    memcpy(&ua, &a, 8);
    memcpy(&ub, &b, 8);
    asm("add.rn.f32x2 %0, %1, %2;" : "=l"(ur) : "l"(ua), "l"(ub));
    float2 r;
    memcpy(&r, &ur, 8);
    return r;
}

// ---------------------------------------------------------------------------
// Kernel 1: emit[row,y] = sum_d X[row,d]*W[d,y], cuBLAS sliced1x4 ordering
// (identical per-accumulator FMA sequence + serial z-combine as the R4 kernel
// that verified bit-exact). Restructured z-outer so X is read once.
// ---------------------------------------------------------------------------
__global__ void __launch_bounds__(256) emit_kernel(const float* __restrict__ X,
                                                   const float* __restrict__ W) {
    __shared__ float Wt[YY * DD];  // Wt[y*128 + d] = W[d*26 + y]
    int tid = threadIdx.x;
    for (int i = tid; i < YY * DD; i += 256) {
        int y = i / DD, d = i % DD;
        Wt[i] = W[d * YY + y];
    }
    __syncthreads();

    int row = blockIdx.x * 256 + tid;
    const float4* xr = (const float4*)(X + (size_t)row * DD);
    const float4* wt4 = (const float4*)Wt;  // [y][32] float4

    float r[YY], s[YY];
#pragma unroll
    for (int z = 0; z < 4; z++) {
#pragma unroll
        for (int y = 0; y < YY; y++) s[y] = 0.f;
#pragma unroll
        for (int t = 0; t < 4; t++) {
            int c = 8 * t + 2 * z;  // float4 index; chunk k = 32t+8z
            float4 xa = xr[c];
            float4 xb = xr[c + 1];
#pragma unroll
            for (int y = 0; y < YY; y++) {
                float4 w0 = wt4[y * 32 + c];
                float4 w1 = wt4[y * 32 + c + 1];
                float acc = s[y];
                acc = fmaf(xa.x, w0.x, acc);
                acc = fmaf(xa.y, w0.y, acc);
                acc = fmaf(xa.z, w0.z, acc);
                acc = fmaf(xa.w, w0.w, acc);
                acc = fmaf(xb.x, w1.x, acc);
                acc = fmaf(xb.y, w1.y, acc);
                acc = fmaf(xb.z, w1.z, acc);
                acc = fmaf(xb.w, w1.w, acc);
                s[y] = acc;
            }
        }
#pragma unroll
        for (int y = 0; y < YY; y++)
            r[y] = (z == 0) ? s[y] : __fadd_rn(r[y], s[y]);  // ((s0+s1)+s2)+s3
    }

    float2* er = (float2*)(g_emit + (size_t)row * YY);  // row*104B, 8B aligned
#pragma unroll
    for (int k = 0; k < 13; k++) er[k] = make_float2(r[2 * k], r[2 * k + 1]);
}

// ---------------------------------------------------------------------------
// argmax over 13 float2 pairs (26 values) with FIRST-INDEX tie-breaking.
// Value path uses FMNMX (fmaxf); index path FSETP+SEL with keep-left on >=.
// Left operands always cover lower indices -> first max wins exactly.
// ---------------------------------------------------------------------------
__device__ __forceinline__ void argmax26p(const float2* v2, float& mv, int& mi) {
    float m1[13]; int i1[13];
#pragma unroll
    for (int k = 0; k < 13; k++) {
        float lo = v2[k].x, hi = v2[k].y;
        m1[k] = fmaxf(lo, hi);
        i1[k] = (lo >= hi) ? (2 * k) : (2 * k + 1);
    }
    float m2[7]; int i2[7];
#pragma unroll
    for (int k = 0; k < 6; k++) {
        m2[k] = fmaxf(m1[2 * k], m1[2 * k + 1]);
        i2[k] = (m1[2 * k] >= m1[2 * k + 1]) ? i1[2 * k] : i1[2 * k + 1];
    }
    m2[6] = m1[12]; i2[6] = i1[12];
    float m3[4]; int i3[4];
#pragma unroll
    for (int k = 0; k < 3; k++) {
        m3[k] = fmaxf(m2[2 * k], m2[2 * k + 1]);
        i3[k] = (m2[2 * k] >= m2[2 * k + 1]) ? i2[2 * k] : i2[2 * k + 1];
    }
    m3[3] = m2[6]; i3[3] = i2[6];
    float m4a = fmaxf(m3[0], m3[1]);
    int i4a = (m3[0] >= m3[1]) ? i3[0] : i3[1];
    float m4b = fmaxf(m3[2], m3[3]);
    int i4b = (m3[2] >= m3[3]) ? i3[2] : i3[3];
    mv = fmaxf(m4a, m4b);
    mi = (m4a >= m4b) ? i4a : i4b;
}

// ---------------------------------------------------------------------------
// Kernel 2: Viterbi forward (warp 0) + chunked parallel backtrace (8 warps).
// Exact float semantics: lookup[i][y1] = max_yp ((e[i-1][yp]+T[yp][y1]) + l[yp])
// with first-index argmax; a = (e+T) precomputed off the recurrence chain.
// ---------------------------------------------------------------------------
__global__ void __launch_bounds__(256, 1) viterbi_kernel(const float* __restrict__ Tm,
                                                         float* __restrict__ out) {
    extern __shared__ unsigned char smx[];
    unsigned char* bp = smx;                          // [2049][26] bytes
    float* lbuf = (float*)(smx + 53280);              // [2][28]
    float* ebuf = lbuf + 56;                          // [2][28]
    float* Tt = ebuf + 56;                            // [32][28]
    unsigned char* maps = (unsigned char*)(Tt + 32 * 28);  // [32][32]
    unsigned char* path = maps + 1024;                // [2048]
    int* entries = (int*)(path + 2048);               // [32]

    int tid = threadIdx.x;
    int wid = tid >> 5;
    int lane = tid & 31;
    int b = blockIdx.x;

    // --- init (all threads) ---
    for (int j = tid; j < 56; j += 256) { lbuf[j] = 0.f; ebuf[j] = 0.f; }
    for (int j = tid; j < 32 * 28; j += 256) {
        int ln = j / 28, yp = j % 28;
        Tt[j] = (ln < YY && yp < YY) ? Tm[yp * YY + ln] : 0.f;
    }
    if (tid < YY) bp[2048 * 26 + tid] = (unsigned char)tid;  // identity row
    __syncthreads();

    const float* eb = g_emit + (size_t)b * SS * YY;

    // ======================= forward scan: warp 0 only =======================
    if (wid == 0) {
        float e0 = 0.f, e1 = 0.f, ev_ready = 0.f, ev_fly = 0.f;
        if (lane < YY) {
            e0 = eb[lane];
            e1 = eb[YY + lane];
            ev_ready = eb[2 * YY + lane];
            ev_fly = eb[3 * YY + lane];
            ebuf[lane] = e0;        // slot 0 = e[0]
            ebuf[28 + lane] = e1;   // slot 1 = e[1]
        }
        __syncwarp();

        // per-lane T column, packed pairs (persistent in regs)
        float2 tc2[14];
        {
            const float4* t4 = (const float4*)(Tt + lane * 28);
#pragma unroll
            for (int j = 0; j < 7; j++) {
                float4 tt = t4[j];
                tc2[2 * j] = make_float2(tt.x, tt.y);
                tc2[2 * j + 1] = make_float2(tt.z, tt.w);
            }
        }
        // a2 = e[0] + Tc  (pairs)
        float2 a2[14];
        {
            const float4* e4 = (const float4*)ebuf;  // slot 0
#pragma unroll
            for (int j = 0; j < 7; j++) {
                float4 ee = e4[j];
                a2[2 * j] = addx2(make_float2(ee.x, ee.y), tc2[2 * j]);
                a2[2 * j + 1] = addx2(make_float2(ee.z, ee.w), tc2[2 * j + 1]);
            }
        }

        unsigned char* bprow = bp + 26;  // row i

#pragma unroll 2
        for (int i = 1; i < SS; i++) {
            int pp = (i - 1) & 1;
            int p = i & 1;
            __syncwarp();

            // v = a + l   (critical chain)
            float2 v2[13];
            {
                const float4* l4 = (const float4*)(lbuf + pp * 28);
#pragma unroll
                for (int j = 0; j < 7; j++) {
                    float4 ll = l4[j];
                    v2[2 * j] = addx2(a2[2 * j], make_float2(ll.x, ll.y));
                    if (2 * j + 1 < 13)
                        v2[2 * j + 1] = addx2(a2[2 * j + 1], make_float2(ll.z, ll.w));
                }
            }

            float m; int idx;
            argmax26p(v2, m, idx);

            if (lane < YY) {
                lbuf[p * 28 + lane] = m;
                bprow[lane] = (unsigned char)idx;
            }
            bprow += 26;

            // a_next = e[i] + Tc (off critical chain)
            {
                const float4* e4 = (const float4*)(ebuf + (i & 1) * 28);
#pragma unroll
                for (int j = 0; j < 7; j++) {
                    float4 ee = e4[j];
                    a2[2 * j] = addx2(make_float2(ee.x, ee.y), tc2[2 * j]);
                    a2[2 * j + 1] = addx2(make_float2(ee.z, ee.w), tc2[2 * j + 1]);
                }
            }
            // e-row pipeline: stage e[i+1] into slot (i+1)&1, fetch e[i+3]
            if (lane < YY) ebuf[((i + 1) & 1) * 28 + lane] = ev_ready;
            ev_ready = ev_fly;
            if (lane < YY && (i + 3) < SS) ev_fly = eb[(size_t)(i + 3) * YY + lane];
        }

        // last = argmax(em[S-1] + lookup[S-1]);  em first (reference order)
        __syncwarp();
        {
            const float4* e4 = (const float4*)(ebuf + 28);  // slot1 = e[2047]
            const float4* l4 = (const float4*)(lbuf + 28);  // slot1 = l[2047]
            float2 vv[13];
#pragma unroll
            for (int j = 0; j < 7; j++) {
                float4 ee = e4[j];
                float4 ll = l4[j];
                vv[2 * j] = addx2(make_float2(ee.x, ee.y), make_float2(ll.x, ll.y));
                if (2 * j + 1 < 13)
                    vv[2 * j + 1] = addx2(make_float2(ee.z, ee.w), make_float2(ll.z, ll.w));
            }
            float mm; int last;
            argmax26p(vv, mm, last);
            if (lane == 0) entries[31] = last;
        }
    }
    __syncthreads();

    // ============== Phase A: per-chunk maps (8 warps x 4 chunks) =============
    for (int q = 0; q < 4; q++) {
        int c = wid * 4 + q;
        if (lane < YY) {
            int y = lane;
            int r = (c * 64 + 64) * 26;
            for (int k = 0; k < 64; k++) { y = bp[r + y]; r -= 26; }
            maps[c * 32 + lane] = (unsigned char)y;
        }
    }
    __syncthreads();

    // ============== Phase B: chunk entry labels (serial, 1 thread) ===========
    if (tid == 0) {
        int e = entries[31];
        for (int c = 31; c >= 1; c--) {
            e = maps[c * 32 + e];
            entries[c - 1] = e;
        }
    }
    __syncthreads();

    // ============== Phase C: re-chase chunks in parallel (warp 0) ============
    if (wid == 0) {
        int c = lane;  // 32 chunks, one per lane
        int y = entries[c];
        int r = (c * 64 + 64) * 26;
        for (int k = 63; k >= 0; k--) {
            y = bp[r + y];
            r -= 26;
            path[c * 64 + k] = (unsigned char)y;
        }
    }
    __syncthreads();

    // ============== Phase D: one-hot output (256 threads, float2) ============
    float* ob = out + (size_t)b * SS * YY;
    for (int i = tid; i < SS; i += 256) {
        int lbl = path[i];
        float2* orow = (float2*)(ob + (size_t)i * YY);
#pragma unroll
        for (int k = 0; k < 13; k++) {
            float2 w;
            w.x = (2 * k == lbl) ? 1.f : 0.f;
            w.y = (2 * k + 1 == lbl) ? 1.f : 0.f;
            orow[k] = w;
        }
    }
}

// ---------------------------------------------------------------------------
extern "C" void kernel_launch(void* const* d_in, const int* in_sizes, int n_in,
                              void* d_out, int out_size) {
    const float* X = (const float*)d_in[0];   // [B,S,D]
    const float* W = (const float*)d_in[1];   // [D,Y]
    const float* T = (const float*)d_in[2];   // [Y,Y]
    float* out = (float*)d_out;               // [B,S,Y] fp32

    emit_kernel<<<(BB * SS) / 256, 256>>>(X, W);

    // smem: bp 53280(aligned) + lbuf/ebuf 448 + Tt 3584 + maps 1024
    //       + path 2048 + entries 128 = 60512
    int smem = 60544;
    cudaFuncSetAttribute(viterbi_kernel,
                         cudaFuncAttributeMaxDynamicSharedMemorySize, smem);
    viterbi_kernel<<<BB, 256, smem>>>(T, out);
}

// round 7
// speedup vs baseline: 2.4931x; 2.0900x over previous
#include <cuda_runtime.h>
#include <string.h>

// Problem constants
#define BB 128
#define SS 2048
#define DD 128
#define YY 26

// Scratch for emit = X @ W  (27.3 MB). Static __device__ array: no allocation.
__device__ float g_emit[BB * SS * YY];

// ---------------------------------------------------------------------------
// Packed f32x2 add (two independent fadd.rn — bit-exact vs scalar __fadd_rn).
// ---------------------------------------------------------------------------
__device__ __forceinline__ float2 addx2(float2 a, float2 b) {
    unsigned long long ua, ub, ur;
    memcpy(&ua, &a, 8);
    memcpy(&ub, &b, 8);
    asm("add.rn.f32x2 %0, %1, %2;" : "=l"(ur) : "l"(ua), "l"(ub));
    float2 r;
    memcpy(&r, &ur, 8);
    return r;
}

// ---------------------------------------------------------------------------
// Kernel 1: emit = X @ W with the verified cuBLAS sliced1x4 ordering:
// per accumulator: z-slices over chunks k=32t+8z (ascending t), FMA ascending k,
// serial combine ((s0+s1)+s2)+s3.  2 rows/thread halves W shared traffic.
// ---------------------------------------------------------------------------
__global__ void __launch_bounds__(128) emit_kernel(const float* __restrict__ X,
                                                   const float* __restrict__ W) {
    __shared__ float Wt[YY * DD];  // Wt[y*128 + d] = W[d*26 + y]
    int tid = threadIdx.x;
    for (int i = tid; i < YY * DD; i += 128) {
        int y = i / DD, d = i % DD;
        Wt[i] = W[d * YY + y];
    }
    __syncthreads();

    int r0 = blockIdx.x * 256 + tid;  // rows r0, r0+128
    const float4* xr0 = (const float4*)(X + (size_t)r0 * DD);
    const float4* xr1 = (const float4*)(X + (size_t)(r0 + 128) * DD);
    const float4* wt4 = (const float4*)Wt;  // [y][32] float4

    float ra[YY], rb[YY], sa[YY], sb[YY];
#pragma unroll
    for (int z = 0; z < 4; z++) {
#pragma unroll
        for (int y = 0; y < YY; y++) { sa[y] = 0.f; sb[y] = 0.f; }
#pragma unroll
        for (int t = 0; t < 4; t++) {
            int c = 8 * t + 2 * z;  // float4 index; chunk k = 32t+8z
            float4 xa0 = xr0[c];
            float4 xb0 = xr0[c + 1];
            float4 xa1 = xr1[c];
            float4 xb1 = xr1[c + 1];
#pragma unroll
            for (int y = 0; y < YY; y++) {
                float4 w0 = wt4[y * 32 + c];
                float4 w1 = wt4[y * 32 + c + 1];
                float A = sa[y];
                A = fmaf(xa0.x, w0.x, A);
                A = fmaf(xa0.y, w0.y, A);
                A = fmaf(xa0.z, w0.z, A);
                A = fmaf(xa0.w, w0.w, A);
                A = fmaf(xb0.x, w1.x, A);
                A = fmaf(xb0.y, w1.y, A);
                A = fmaf(xb0.z, w1.z, A);
                A = fmaf(xb0.w, w1.w, A);
                sa[y] = A;
                float Bv = sb[y];
                Bv = fmaf(xa1.x, w0.x, Bv);
                Bv = fmaf(xa1.y, w0.y, Bv);
                Bv = fmaf(xa1.z, w0.z, Bv);
                Bv = fmaf(xa1.w, w0.w, Bv);
                Bv = fmaf(xb1.x, w1.x, Bv);
                Bv = fmaf(xb1.y, w1.y, Bv);
                Bv = fmaf(xb1.z, w1.z, Bv);
                Bv = fmaf(xb1.w, w1.w, Bv);
                sb[y] = Bv;
            }
        }
#pragma unroll
        for (int y = 0; y < YY; y++) {
            ra[y] = (z == 0) ? sa[y] : __fadd_rn(ra[y], sa[y]);
            rb[y] = (z == 0) ? sb[y] : __fadd_rn(rb[y], sb[y]);
        }
    }

    float2* e0 = (float2*)(g_emit + (size_t)r0 * YY);
    float2* e1 = (float2*)(g_emit + (size_t)(r0 + 128) * YY);
#pragma unroll
    for (int k = 0; k < 13; k++) {
        e0[k] = make_float2(ra[2 * k], ra[2 * k + 1]);
        e1[k] = make_float2(rb[2 * k], rb[2 * k + 1]);
    }
}

// ---------------------------------------------------------------------------
// argmax over 13 float2 pairs (26 values) with FIRST-INDEX tie-breaking.
// Value path FMNMX; index path FSETP+SEL, keep-left on >= (left = lower idx).
// ---------------------------------------------------------------------------
__device__ __forceinline__ void argmax26p(const float2* v2, float& mv, int& mi) {
    float m1[13]; int i1[13];
#pragma unroll
    for (int k = 0; k < 13; k++) {
        float lo = v2[k].x, hi = v2[k].y;
        m1[k] = fmaxf(lo, hi);
        i1[k] = (lo >= hi) ? (2 * k) : (2 * k + 1);
    }
    float m2[7]; int i2[7];
#pragma unroll
    for (int k = 0; k < 6; k++) {
        m2[k] = fmaxf(m1[2 * k], m1[2 * k + 1]);
        i2[k] = (m1[2 * k] >= m1[2 * k + 1]) ? i1[2 * k] : i1[2 * k + 1];
    }
    m2[6] = m1[12]; i2[6] = i1[12];
    float m3[4]; int i3[4];
#pragma unroll
    for (int k = 0; k < 3; k++) {
        m3[k] = fmaxf(m2[2 * k], m2[2 * k + 1]);
        i3[k] = (m2[2 * k] >= m2[2 * k + 1]) ? i2[2 * k] : i2[2 * k + 1];
    }
    m3[3] = m2[6]; i3[3] = i2[6];
    float m4a = fmaxf(m3[0], m3[1]);
    int i4a = (m3[0] >= m3[1]) ? i3[0] : i3[1];
    float m4b = fmaxf(m3[2], m3[3]);
    int i4b = (m3[2] >= m3[3]) ? i3[2] : i3[3];
    mv = fmaxf(m4a, m4b);
    mi = (m4a >= m4b) ? i4a : i4b;
}

// ---------------------------------------------------------------------------
// Shared-memory layout (dynamic), byte offsets:
//   etile  : 2*128*32 floats   =  32768 B   @ 0
//   bp     : 2049*32  bytes    =  65568 B   @ 32768
//   lbuf   : 2*32 floats       =    256 B   @ 98336
//   Tt     : 32*32 floats      =   4096 B   @ 98592
//   maps   : 32*32 bytes       =   1024 B   @ 102688
//   path   : 2048 bytes        =   2048 B   @ 103712
//   entries: 32 ints           =    128 B   @ 105760
//   total                      = 105888 B
// ---------------------------------------------------------------------------
#define OFF_ETILE 0
#define OFF_BP 32768
#define OFF_LBUF 98336
#define OFF_TT 98592
#define OFF_MAPS 102688
#define OFF_PATH 103712
#define OFF_ENTRIES 105760
#define SMEM_TOTAL 105888

// ---------------------------------------------------------------------------
// Kernel 2: Viterbi forward (warp 0, divergence-free) with producer warps 1-7
// staging emit tiles into shared; then chunked parallel backtrace + output.
// Exact reference semantics: l[i][y1] = max_yp ((e[i-1][yp]+T[yp][y1]) + l[yp]),
// first-index argmax.
// ---------------------------------------------------------------------------
__global__ void __launch_bounds__(256, 1) viterbi_kernel(const float* __restrict__ Tm,
                                                         float* __restrict__ out) {
    extern __shared__ unsigned char smx[];
    float* etile = (float*)(smx + OFF_ETILE);          // [2][128][32]
    unsigned char* bp = smx + OFF_BP;                  // [2049][32]
    float* lbuf = (float*)(smx + OFF_LBUF);            // [2][32]
    float* Tt = (float*)(smx + OFF_TT);                // [32][32]
    unsigned char* maps = smx + OFF_MAPS;              // [32][32]
    unsigned char* path = smx + OFF_PATH;              // [2048]
    int* entries = (int*)(smx + OFF_ENTRIES);          // [32]

    int tid = threadIdx.x;
    int wid = tid >> 5;
    int lane = tid & 31;
    int b = blockIdx.x;
    const float* eb = g_emit + (size_t)b * SS * YY;

    // --- init (all 256 threads) ---
    if (tid < 64) lbuf[tid] = 0.f;
    for (int j = tid; j < 32 * 32; j += 256) {
        int ln = j >> 5, yp = j & 31;
        Tt[j] = (ln < YY && yp < YY) ? Tm[yp * YY + ln] : 0.f;
    }
    if (tid < 32) bp[2048 * 32 + tid] = (unsigned char)(tid < YY ? tid : 0);
    // prologue: everyone fills tile 0 (buf 0)
    for (int j = tid; j < 128 * YY; j += 256) {
        etile[(j / YY) * 32 + (j % YY)] = eb[j];
    }
    __syncthreads();

    // per-lane T column as 13 packed pairs (persistent registers, warp 0 path)
    float2 tc2[13], a2[13];
    if (wid == 0) {
        const float4* t4 = (const float4*)(Tt + lane * 32);
#pragma unroll
        for (int j = 0; j < 7; j++) {
            float4 tt = t4[j];
            if (2 * j < 13) tc2[2 * j] = make_float2(tt.x, tt.y);
            if (2 * j + 1 < 13) tc2[2 * j + 1] = make_float2(tt.z, tt.w);
        }
        // a2 = e[0] + Tc
        const float4* e4 = (const float4*)etile;  // buf0 row 0
#pragma unroll
        for (int j = 0; j < 7; j++) {
            float4 ee = e4[j];
            if (2 * j < 13) a2[2 * j] = addx2(make_float2(ee.x, ee.y), tc2[2 * j]);
            if (2 * j + 1 < 13)
                a2[2 * j + 1] = addx2(make_float2(ee.z, ee.w), tc2[2 * j + 1]);
        }
    }

    // ===================== tiled forward scan =====================
    for (int t = 0; t < 16; t++) {
        if (wid == 0) {
            const float* etb = etile + (t & 1) * 128 * 32;
            unsigned char* bprow = bp + (size_t)(t == 0 ? 1 : t * 128) * 32;
            int i0 = (t == 0) ? 1 : t * 128;
            int i1 = t * 128 + 128;
#pragma unroll 2
            for (int i = i0; i < i1; i++) {
                __syncwarp();
                // v = a + l  (critical chain)
                float2 v2[13];
                {
                    const float4* l4 = (const float4*)(lbuf + ((i - 1) & 1) * 32);
#pragma unroll
                    for (int j = 0; j < 7; j++) {
                        float4 ll = l4[j];
                        if (2 * j < 13)
                            v2[2 * j] = addx2(a2[2 * j], make_float2(ll.x, ll.y));
                        if (2 * j + 1 < 13)
                            v2[2 * j + 1] = addx2(a2[2 * j + 1], make_float2(ll.z, ll.w));
                    }
                }
                float m; int idx;
                argmax26p(v2, m, idx);

                lbuf[(i & 1) * 32 + lane] = m;        // all lanes (pad harmless)
                bprow[lane] = (unsigned char)idx;     // all lanes (pad harmless)
                bprow += 32;

                // a_next = e[i] + Tc  (off the critical chain)
                {
                    const float4* e4 = (const float4*)(etb + (i & 127) * 32);
#pragma unroll
                    for (int j = 0; j < 7; j++) {
                        float4 ee = e4[j];
                        if (2 * j < 13)
                            a2[2 * j] = addx2(make_float2(ee.x, ee.y), tc2[2 * j]);
                        if (2 * j + 1 < 13)
                            a2[2 * j + 1] = addx2(make_float2(ee.z, ee.w), tc2[2 * j + 1]);
                    }
                }
            }
        } else if (t + 1 < 16) {
            // producers: stage tile t+1 into buf (t+1)&1
            float* dst = etile + ((t + 1) & 1) * 128 * 32;
            const float* src = eb + (size_t)(t + 1) * 128 * YY;
            for (int j = (wid - 1) * 32 + lane; j < 128 * YY; j += 224) {
                dst[(j / YY) * 32 + (j % YY)] = src[j];
            }
        }
        __syncthreads();
    }

    // last = argmax(em[S-1] + lookup[S-1])  (em first, reference order)
    if (wid == 0) {
        const float4* e4 = (const float4*)(etile + 128 * 32 + 127 * 32);  // buf1,row127
        const float4* l4 = (const float4*)(lbuf + 32);                    // parity of 2047
        float2 vv[13];
#pragma unroll
        for (int j = 0; j < 7; j++) {
            float4 ee = e4[j];
            float4 ll = l4[j];
            if (2 * j < 13)
                vv[2 * j] = addx2(make_float2(ee.x, ee.y), make_float2(ll.x, ll.y));
            if (2 * j + 1 < 13)
                vv[2 * j + 1] = addx2(make_float2(ee.z, ee.w), make_float2(ll.z, ll.w));
        }
        float mm; int last;
        argmax26p(vv, mm, last);
        if (lane == 0) entries[31] = last;
    }
    __syncthreads();

    // ===== Phase A: per-chunk composed maps (8 warps x 4 chunks of 64) =====
    for (int q = 0; q < 4; q++) {
        int c = wid * 4 + q;
        if (lane < YY) {
            int y = lane;
            int r = (c * 64 + 64) * 32;
            for (int k = 0; k < 64; k++) { y = bp[r + y]; r -= 32; }
            maps[c * 32 + lane] = (unsigned char)y;
        }
    }
    __syncthreads();

    // ===== Phase B: chunk entry labels (serial, 1 thread) =====
    if (tid == 0) {
        int e = entries[31];
        for (int c = 31; c >= 1; c--) {
            e = maps[c * 32 + e];
            entries[c - 1] = e;
        }
    }
    __syncthreads();

    // ===== Phase C: re-chase chunks in parallel (warp 0, 1 chunk/lane) =====
    if (wid == 0) {
        int c = lane;
        int y = entries[c];
        int r = (c * 64 + 64) * 32;
        for (int k = 63; k >= 0; k--) {
            y = bp[r + y];
            r -= 32;
            path[c * 64 + k] = (unsigned char)y;
        }
    }
    __syncthreads();

    // ===== Phase D: one-hot output (256 threads, float2 rows) =====
    float* ob = out + (size_t)b * SS * YY;
    for (int i = tid; i < SS; i += 256) {
        int lbl = path[i];
        float2* orow = (float2*)(ob + (size_t)i * YY);
#pragma unroll
        for (int k = 0; k < 13; k++) {
            float2 w;
            w.x = (2 * k == lbl) ? 1.f : 0.f;
            w.y = (2 * k + 1 == lbl) ? 1.f : 0.f;
            orow[k] = w;
        }
    }
}

// ---------------------------------------------------------------------------
extern "C" void kernel_launch(void* const* d_in, const int* in_sizes, int n_in,
                              void* d_out, int out_size) {
    const float* X = (const float*)d_in[0];   // [B,S,D]
    const float* W = (const float*)d_in[1];   // [D,Y]
    const float* T = (const float*)d_in[2];   // [Y,Y]
    float* out = (float*)d_out;               // [B,S,Y] fp32

    emit_kernel<<<(BB * SS) / 256, 128>>>(X, W);

    cudaFuncSetAttribute(viterbi_kernel,
                         cudaFuncAttributeMaxDynamicSharedMemorySize, SMEM_TOTAL);
    viterbi_kernel<<<BB, 256, SMEM_TOTAL>>>(T, out);
}

// round 8
// speedup vs baseline: 3.5160x; 1.4103x over previous
#include <cuda_runtime.h>

// Problem constants
#define BB 128
#define SS 2048
#define DD 128
#define YY 26

typedef unsigned long long u64;

// ---- packed f32x2 helpers (each = two independent .rn ops; bit-exact) ----
__device__ __forceinline__ u64 pack2(float x, float y) {
    u64 r; asm("mov.b64 %0, {%1,%2};" : "=l"(r) : "f"(x), "f"(y)); return r;
}
__device__ __forceinline__ float2 unpack2(u64 u) {
    float2 f; asm("mov.b64 {%0,%1}, %2;" : "=f"(f.x), "=f"(f.y) : "l"(u)); return f;
}
__device__ __forceinline__ u64 add2(u64 a, u64 b) {
    u64 d; asm("add.rn.f32x2 %0, %1, %2;" : "=l"(d) : "l"(a), "l"(b)); return d;
}
__device__ __forceinline__ u64 fma2(u64 a, u64 b, u64 c) {
    u64 d; asm("fma.rn.f32x2 %0, %1, %2, %3;" : "=l"(d) : "l"(a), "l"(b), "l"(c)); return d;
}

// ---------------------------------------------------------------------------
// Emit one row: e[y] = sum_d x[d]*W[d][y], verified cuBLAS sliced1x4 ordering:
// slice z accumulates chunks k=32t+8z (ascending t, ascending k), FMA; then
// ((s0+s1)+s2)+s3.  Packed over y-pairs: each half has the exact scalar
// fma.rn / add.rn sequence of the verified kernel.
// Ws: padded [128][32] rows (W[d][y], y<26).  dst: 32-float padded row.
// ---------------------------------------------------------------------------
__device__ __forceinline__ void emit_row(const float* __restrict__ xrow,
                                         const float* __restrict__ Ws,
                                         float* __restrict__ dst) {
    const float4* xr = (const float4*)xrow;
    u64 r2[13], s2[13];
#pragma unroll
    for (int z = 0; z < 4; z++) {
#pragma unroll
        for (int k = 0; k < 13; k++) s2[k] = 0ULL;
#pragma unroll
        for (int t = 0; t < 4; t++) {
            int c = 8 * t + 2 * z;  // float4 index; chunk k = 32t+8z
            float4 xa = xr[c];
            float4 xb = xr[c + 1];
            float xs[8] = {xa.x, xa.y, xa.z, xa.w, xb.x, xb.y, xb.z, xb.w};
#pragma unroll
            for (int kk = 0; kk < 8; kk++) {
                u64 xx = pack2(xs[kk], xs[kk]);
                const u64* wr = (const u64*)(Ws + (c * 4 + kk) * 32);
#pragma unroll
                for (int j = 0; j < 13; j++) s2[j] = fma2(xx, wr[j], s2[j]);
            }
        }
#pragma unroll
        for (int k = 0; k < 13; k++) r2[k] = (z == 0) ? s2[k] : add2(r2[k], s2[k]);
    }
    float2* d2 = (float2*)dst;
#pragma unroll
    for (int k = 0; k < 13; k++) d2[k] = unpack2(r2[k]);
}

// ---------------------------------------------------------------------------
// Value-only max over 26 (selection is exact; any combine order gives the
// same bits as jnp.max).
// ---------------------------------------------------------------------------
__device__ __forceinline__ float max26(const float2* v) {
    float m1[13];
#pragma unroll
    for (int k = 0; k < 13; k++) m1[k] = fmaxf(v[k].x, v[k].y);
    float m2[7];
#pragma unroll
    for (int k = 0; k < 6; k++) m2[k] = fmaxf(m1[2 * k], m1[2 * k + 1]);
    m2[6] = m1[12];
    float a = fmaxf(m2[0], m2[1]);
    float b = fmaxf(m2[2], m2[3]);
    float c = fmaxf(m2[4], m2[5]);
    return fmaxf(fmaxf(a, b), fmaxf(c, m2[6]));
}

// Full first-index argmax (keep-left on >=, left covers lower indices).
__device__ __forceinline__ void argmax26p(const float2* v2, float& mv, int& mi) {
    float m1[13]; int i1[13];
#pragma unroll
    for (int k = 0; k < 13; k++) {
        float lo = v2[k].x, hi = v2[k].y;
        m1[k] = fmaxf(lo, hi);
        i1[k] = (lo >= hi) ? (2 * k) : (2 * k + 1);
    }
    float m2[7]; int i2[7];
#pragma unroll
    for (int k = 0; k < 6; k++) {
        m2[k] = fmaxf(m1[2 * k], m1[2 * k + 1]);
        i2[k] = (m1[2 * k] >= m1[2 * k + 1]) ? i1[2 * k] : i1[2 * k + 1];
    }
    m2[6] = m1[12]; i2[6] = i1[12];
    float m3[4]; int i3[4];
#pragma unroll
    for (int k = 0; k < 3; k++) {
        m3[k] = fmaxf(m2[2 * k], m2[2 * k + 1]);
        i3[k] = (m2[2 * k] >= m2[2 * k + 1]) ? i2[2 * k] : i2[2 * k + 1];
    }
    m3[3] = m2[6]; i3[3] = i2[6];
    float a = fmaxf(m3[0], m3[1]);
    int ia = (m3[0] >= m3[1]) ? i3[0] : i3[1];
    float bq = fmaxf(m3[2], m3[3]);
    int ib = (m3[2] >= m3[3]) ? i3[2] : i3[3];
    mv = fmaxf(a, bq);
    mi = (a >= bq) ? ia : ib;
}

// ---------------------------------------------------------------------------
// bp for one (i, y1=lane): first-index argmax over yp of (e[yp]+T[yp][y1])+l[yp]
// Serial ascending scan with strict > == jnp.argmax first-occurrence.
// ---------------------------------------------------------------------------
__device__ __forceinline__ int bp_argmax(const float* __restrict__ erow,
                                         const float* __restrict__ lrow,
                                         const u64* __restrict__ tcc) {
    float2 v[13];
    const float4* e4 = (const float4*)erow;
    const float4* l4 = (const float4*)lrow;
#pragma unroll
    for (int j = 0; j < 7; j++) {
        float4 e = e4[j];
        float4 l = l4[j];
        u64 a = add2(pack2(e.x, e.y), tcc[2 * j]);
        v[2 * j] = unpack2(add2(a, pack2(l.x, l.y)));
        if (2 * j + 1 < 13) {
            u64 bq = add2(pack2(e.z, e.w), tcc[2 * j + 1]);
            v[2 * j + 1] = unpack2(add2(bq, pack2(l.z, l.w)));
        }
    }
    float best = v[0].x;
    int idx = 0;
#pragma unroll
    for (int k = 0; k < 13; k++) {
        float lo = v[k].x, hi = v[k].y;
        if (k > 0 && lo > best) { best = lo; idx = 2 * k; }
        if (hi > best) { best = hi; idx = 2 * k + 1; }
    }
    return idx;
}

// ---------------------------------------------------------------------------
// Shared layout (bytes):
//   ebuf   : 3*128*32 f = 49152   @ 0        (3-deep emit-row ring, tile m -> m%3)
//   lring  : 384*32 f   = 49152   @ 49152    (l rows, row i -> i%384)
//   Ws     : 128*32 f   = 16384   @ 98304
//   Tt     : 32*32 f    =  4096   @ 114688
//   bp     : 2049*32 B  = 65568   @ 118784
//   maps   : 1024 B               @ 184352
//   path   : 2048 B               @ 185376
//   entries: 32*4 B               @ 187424
// ---------------------------------------------------------------------------
#define OFF_EBUF 0
#define OFF_LRING 49152
#define OFF_WS 98304
#define OFF_TT 114688
#define OFF_BP 118784
#define OFF_MAPS 184352
#define OFF_PATH 185376
#define OFF_ENT 187424
#define SMEM_TOTAL 187552

__global__ void __launch_bounds__(256, 1) crf_kernel(const float* __restrict__ X,
                                                     const float* __restrict__ W,
                                                     const float* __restrict__ Tm,
                                                     float* __restrict__ out) {
    extern __shared__ unsigned char smx[];
    float* ebuf = (float*)(smx + OFF_EBUF);
    float* lring = (float*)(smx + OFF_LRING);
    float* Ws = (float*)(smx + OFF_WS);
    float* Tt = (float*)(smx + OFF_TT);
    unsigned char* bp = smx + OFF_BP;
    unsigned char* maps = smx + OFF_MAPS;
    unsigned char* path = smx + OFF_PATH;
    int* entries = (int*)(smx + OFF_ENT);

    int tid = threadIdx.x;
    int wid = tid >> 5;
    int lane = tid & 31;
    int b = blockIdx.x;
    const float* Xb = X + (size_t)b * SS * DD;

    // ---- init ----
    for (int j = tid; j < 128 * 32; j += 256) {
        int k = j >> 5, y = j & 31;
        Ws[j] = (y < YY) ? W[k * YY + y] : 0.f;
    }
    for (int j = tid; j < 32 * 32; j += 256) {
        int ln = j >> 5, yp = j & 31;
        Tt[j] = (ln < YY && yp < YY) ? Tm[yp * YY + ln] : 0.f;
    }
    if (tid < 32) lring[tid] = 0.f;                                   // l[0] = 0
    if (tid < 32) bp[2048 * 32 + tid] = (unsigned char)(tid < YY ? tid : 0);
    __syncthreads();

    // ---- prologue: emit tile 0 into ebuf[0] ----
    if (tid < 128) emit_row(Xb + (size_t)tid * DD, Ws, ebuf + tid * 32);
    __syncthreads();

    // per-lane T column as packed pairs (all warps)
    u64 tcc[13];
    {
        const float4* t4 = (const float4*)(Tt + lane * 32);
#pragma unroll
        for (int j = 0; j < 7; j++) {
            float4 t = t4[j];
            tcc[2 * j] = pack2(t.x, t.y);
            if (2 * j + 1 < 13) tcc[2 * j + 1] = pack2(t.z, t.w);
        }
    }

    // warp-0 persistent state
    u64 a2[13];
    float* lw = lring + 32;        // write ptr: row 1
    const float* lr = lring;       // read ptr: row 0
    if (wid == 0) {
        const float4* e4 = (const float4*)ebuf;  // e[0]
#pragma unroll
        for (int j = 0; j < 7; j++) {
            float4 e = e4[j];
            a2[2 * j] = add2(pack2(e.x, e.y), tcc[2 * j]);
            if (2 * j + 1 < 13) a2[2 * j + 1] = add2(pack2(e.z, e.w), tcc[2 * j + 1]);
        }
    }

    // =========================== 16 phases ===========================
    for (int p = 0; p < 16; p++) {
        if (wid == 0) {
            // scan tile p: steps i in [max(1, p*128), p*128+128)
            const float* etb = ebuf + (p % 3) * 4096;
            int i0 = (p == 0) ? 1 : p * 128;
            int i1 = p * 128 + 128;
#pragma unroll 2
            for (int i = i0; i < i1; i++) {
                // v = a + l  (critical chain)
                float2 v[13];
                const float4* l4 = (const float4*)lr;
#pragma unroll
                for (int j = 0; j < 7; j++) {
                    float4 l = l4[j];
                    v[2 * j] = unpack2(add2(a2[2 * j], pack2(l.x, l.y)));
                    if (2 * j + 1 < 13)
                        v[2 * j + 1] = unpack2(add2(a2[2 * j + 1], pack2(l.z, l.w)));
                }
                float m = max26(v);
                lw[lane] = m;  // l[i]
                // a_next = e[i] + Tc  (off the chain)
                const float4* e4 = (const float4*)(etb + (i & 127) * 32);
#pragma unroll
                for (int j = 0; j < 7; j++) {
                    float4 e = e4[j];
                    a2[2 * j] = add2(pack2(e.x, e.y), tcc[2 * j]);
                    if (2 * j + 1 < 13)
                        a2[2 * j + 1] = add2(pack2(e.z, e.w), tcc[2 * j + 1]);
                }
                __syncwarp();
                lr = lw;
                lw += 32;
                if (lw == lring + 384 * 32) lw = lring;
            }
        } else {
            // --- consumers: bp for tile p-1 ---
            if (p >= 1) {
                int tt = p - 1;
                for (int r = wid - 1; r < 128; r += 7) {
                    int i = tt * 128 + r;
                    if (i > 0) {
                        const float* erow = (r > 0)
                            ? (ebuf + (tt % 3) * 4096 + (r - 1) * 32)
                            : (ebuf + ((tt + 2) % 3) * 4096 + 127 * 32);
                        const float* lrow = lring + ((i - 1) % 384) * 32;
                        int idx = bp_argmax(erow, lrow, tcc);
                        if (lane < YY) bp[i * 32 + lane] = (unsigned char)idx;
                    }
                }
            }
            // boundary e-row reads above must precede the emit overwrite below
            asm volatile("bar.sync 1, 224;" ::: "memory");
            // --- consumers: emit tile p+1 ---
            if (p + 1 < 16) {
                int cid = tid - 32;
                if (cid < 128) {
                    emit_row(Xb + (size_t)((p + 1) * 128 + cid) * DD, Ws,
                             ebuf + ((p + 1) % 3) * 4096 + cid * 32);
                }
            }
        }
        __syncthreads();
    }

    // ====================== epilogue ======================
    if (wid == 0) {
        // last = argmax(em[2047] + lookup[2047])  (em first, reference order)
        const float4* e4 = (const float4*)(ebuf + 0 * 4096 + 127 * 32);  // tile15 -> ebuf[0]
        const float4* l4 = (const float4*)(lring + 127 * 32);            // 2047 % 384 = 127
        float2 vv[13];
#pragma unroll
        for (int j = 0; j < 7; j++) {
            float4 e = e4[j];
            float4 l = l4[j];
            vv[2 * j] = unpack2(add2(pack2(e.x, e.y), pack2(l.x, l.y)));
            if (2 * j + 1 < 13)
                vv[2 * j + 1] = unpack2(add2(pack2(e.z, e.w), pack2(l.z, l.w)));
        }
        float mm; int last;
        argmax26p(vv, mm, last);
        if (lane == 0) entries[31] = last;
    } else {
        // bp for tile 15
        int tt = 15;
        for (int r = wid - 1; r < 128; r += 7) {
            int i = tt * 128 + r;
            const float* erow = (r > 0)
                ? (ebuf + (tt % 3) * 4096 + (r - 1) * 32)
                : (ebuf + ((tt + 2) % 3) * 4096 + 127 * 32);
            const float* lrow = lring + ((i - 1) % 384) * 32;
            int idx = bp_argmax(erow, lrow, tcc);
            if (lane < YY) bp[i * 32 + lane] = (unsigned char)idx;
        }
    }
    __syncthreads();

    // ===== Phase A: per-chunk composed maps (8 warps x 4 chunks of 64) =====
    for (int q = 0; q < 4; q++) {
        int c = wid * 4 + q;
        if (lane < YY) {
            int y = lane;
            int r = (c * 64 + 64) * 32;
            for (int k = 0; k < 64; k++) { y = bp[r + y]; r -= 32; }
            maps[c * 32 + lane] = (unsigned char)y;
        }
    }
    __syncthreads();

    // ===== Phase B: chunk entry labels (serial, 1 thread) =====
    if (tid == 0) {
        int e = entries[31];
        for (int c = 31; c >= 1; c--) {
            e = maps[c * 32 + e];
            entries[c - 1] = e;
        }
    }
    __syncthreads();

    // ===== Phase C: re-chase chunks in parallel (warp 0, 1 chunk/lane) =====
    if (wid == 0) {
        int c = lane;
        int y = entries[c];
        int r = (c * 64 + 64) * 32;
        for (int k = 63; k >= 0; k--) {
            y = bp[r + y];
            r -= 32;
            path[c * 64 + k] = (unsigned char)y;
        }
    }
    __syncthreads();

    // ===== Phase D: one-hot output (256 threads, float2 rows) =====
    float* ob = out + (size_t)b * SS * YY;
    for (int i = tid; i < SS; i += 256) {
        int lbl = path[i];
        float2* orow = (float2*)(ob + (size_t)i * YY);
#pragma unroll
        for (int k = 0; k < 13; k++) {
            float2 w;
            w.x = (2 * k == lbl) ? 1.f : 0.f;
            w.y = (2 * k + 1 == lbl) ? 1.f : 0.f;
            orow[k] = w;
        }
    }
}

// ---------------------------------------------------------------------------
extern "C" void kernel_launch(void* const* d_in, const int* in_sizes, int n_in,
                              void* d_out, int out_size) {
    const float* X = (const float*)d_in[0];   // [B,S,D]
    const float* W = (const float*)d_in[1];   // [D,Y]
    const float* T = (const float*)d_in[2];   // [Y,Y]
    float* out = (float*)d_out;               // [B,S,Y] fp32

    cudaFuncSetAttribute(crf_kernel,
                         cudaFuncAttributeMaxDynamicSharedMemorySize, SMEM_TOTAL);
    crf_kernel<<<BB, 256, SMEM_TOTAL>>>(X, W, T, out);
}